// round 7
// baseline (speedup 1.0000x reference)
#include <cuda_runtime.h>
#include <cstdint>

// ---------------- problem constants ----------------
#define D_H   2048
#define T_LEN 4096
#define NROWS 8192
#define G_DIM 2048
#define KW    4
#define FLATC 8192
#define KDIM  2048

// ---------------- tiling ----------------
#define BM 128
#define BN 128
#define BK 32
#define KCHUNKS (KDIM / BK)               // 64
#define ROW_BYTES 144                     // 128B data + 16B pad (conflict-free LDS.128)
#define SM_BOFF (BM * ROW_BYTES)          // 18432
#define STAGE_BYTES (2 * BM * ROW_BYTES)  // 36864
#define SMEM_TOTAL (2 * STAGE_BYTES)      // 73728

// ---------------- device scratch (tf32-rna + 32-block k-permuted) ----------------
__device__ float g_H  [(size_t)NROWS * G_DIM];
__device__ float g_xc [(size_t)NROWS * D_H];
__device__ float g_w1c[(size_t)G_DIM * D_H];
__device__ float g_w2c[(size_t)FLATC * G_DIM];

__device__ __forceinline__ float silu_f(float v) { return v / (1.0f + __expf(-v)); }
__device__ __forceinline__ uint32_t f2tf32(float x) {
    uint32_t r; asm("cvt.rna.tf32.f32 %0, %1;" : "=r"(r) : "f"(x)); return r;
}
__device__ __forceinline__ float rnd_tf32(float x) { return __uint_as_float(f2tf32(x)); }

__device__ __forceinline__ void cp_async16(uint32_t dst, const void* src) {
    asm volatile("cp.async.cg.shared.global [%0], [%1], 16;" :: "r"(dst), "l"(src));
}
__device__ __forceinline__ uint32_t smem_u32(const void* p) {
    uint32_t a;
    asm("{ .reg .u64 t; cvta.to.shared.u64 t, %1; cvt.u32.u64 %0, t; }" : "=r"(a) : "l"(p));
    return a;
}
__device__ __forceinline__ void lds128(uint32_t addr, uint32_t v[4]) {
    asm volatile("ld.shared.v4.b32 {%0,%1,%2,%3}, [%4];"
                 : "=r"(v[0]), "=r"(v[1]), "=r"(v[2]), "=r"(v[3]) : "r"(addr));
}
__device__ __forceinline__ void mma_tf32(float c[4], uint32_t a0, uint32_t a1,
                                         uint32_t a2, uint32_t a3,
                                         uint32_t b0, uint32_t b1) {
    asm volatile(
        "mma.sync.aligned.m16n8k8.row.col.f32.tf32.tf32.f32 "
        "{%0,%1,%2,%3}, {%4,%5,%6,%7}, {%8,%9}, {%0,%1,%2,%3};"
        : "+f"(c[0]), "+f"(c[1]), "+f"(c[2]), "+f"(c[3])
        : "r"(a0), "r"(a1), "r"(a2), "r"(a3), "r"(b0), "r"(b1));
}

// ---------------- pre-convert: fp32 -> tf32(rna) + 32-block k-permute ----------
// newpos(j) = (j&3)*8 + (j>>3)*2 + ((j>>2)&1)   within each 32-block
// inv(p)    = ((p>>1)&3)*8 + (p&1)*4 + (p>>3)
// One warp per 32-float block: load + store stay inside one 128B line.
template <int WHICH>
__global__ __launch_bounds__(256)
void cvt_perm_kernel(const float* __restrict__ src, int nelem) {
    float* dst = (WHICH == 0) ? g_xc : (WHICH == 1) ? g_w1c : g_w2c;
    int i = blockIdx.x * 256 + threadIdx.x;
    if (i < nelem) {
        int base = i & ~31;
        int p = i & 31;
        int j = ((p >> 1) & 3) * 8 + (p & 1) * 4 + (p >> 3);
        dst[base + p] = rnd_tf32(src[base + j]);
    }
}

// ---------------- tile loader ----------------
__device__ __forceinline__ void load_chunk(const float* __restrict__ A,
                                           const float* __restrict__ B,
                                           uint32_t stagebase, int k0,
                                           int row0, int col0, int tid) {
#pragma unroll
    for (int j = 0; j < 4; j++) {
        int idx = tid + 256 * j;
        int r = idx >> 3, c = idx & 7;
        cp_async16(stagebase + r * ROW_BYTES + c * 16,
                   A + (size_t)(row0 + r) * KDIM + k0 + c * 4);
    }
#pragma unroll
    for (int j = 0; j < 4; j++) {
        int idx = tid + 256 * j;
        int r = idx >> 3, c = idx & 7;
        cp_async16(stagebase + SM_BOFF + r * ROW_BYTES + c * 16,
                   B + (size_t)(col0 + r) * KDIM + k0 + c * 4);
    }
}

// ---------------- main GEMM: C[128x128] = A[128x2048] * B[128x2048]^T ----------
template <int EPI>
__global__ __launch_bounds__(256, 2)
void gemm_mma(const float* __restrict__ X,
              const float* __restrict__ b2,
              float* __restrict__ out) {
    const float* A = (EPI == 0) ? (const float*)g_xc : (const float*)g_H;
    const float* B = (EPI == 0) ? (const float*)g_w1c : (const float*)g_w2c;

    extern __shared__ char smem[];
    const uint32_t sb = smem_u32(smem);
    const int tid  = threadIdx.x;
    const int lane = tid & 31;
    const int warp = tid >> 5;
    const int wm = warp & 3;
    const int wn = warp >> 2;
    const int row0 = blockIdx.y * BM;
    const int col0 = blockIdx.x * BN;
    const int rq = lane >> 2;   // 0..7
    const int kq = lane & 3;    // 0..3

    float acc[2][8][4];
#pragma unroll
    for (int i = 0; i < 2; i++)
#pragma unroll
        for (int j = 0; j < 8; j++)
#pragma unroll
            for (int k = 0; k < 4; k++) acc[i][j][k] = 0.0f;

    load_chunk(A, B, sb, 0, row0, col0, tid);
    asm volatile("cp.async.commit_group;" ::: "memory");

    const uint32_t arow0 = wm * 32 + rq;
    const uint32_t brow0 = wn * 64 + rq;
    const uint32_t kqoff = kq * 32;      // byte offset of this thread's 8-float span

    for (int i = 0; i < KCHUNKS; i++) {
        if (i + 1 < KCHUNKS) {
            load_chunk(A, B, sb + ((i + 1) & 1) * STAGE_BYTES, (i + 1) * BK, row0, col0, tid);
            asm volatile("cp.async.commit_group;" ::: "memory");
            asm volatile("cp.async.wait_group 1;" ::: "memory");
        } else {
            asm volatile("cp.async.wait_group 0;" ::: "memory");
        }
        __syncthreads();

        const uint32_t aB = sb + (i & 1) * STAGE_BYTES;
        const uint32_t bB = aB + SM_BOFF;

#pragma unroll
        for (int h2 = 0; h2 < 2; h2++) {           // two k-step pairs (s = 2h2, 2h2+1)
            const uint32_t off = kqoff + h2 * 16;
            uint32_t av0[2][4], av1[2][4];
#pragma unroll
            for (int mt = 0; mt < 2; mt++) {
                uint32_t r = arow0 + mt * 16;
                lds128(aB + r * ROW_BYTES + off, av0[mt]);            // row
                lds128(aB + (r + 8) * ROW_BYTES + off, av1[mt]);      // row+8
            }
#pragma unroll
            for (int ng = 0; ng < 2; ng++) {       // B rows in groups of 4
                uint32_t bv[4][4];
#pragma unroll
                for (int nt = 0; nt < 4; nt++)
                    lds128(bB + (brow0 + (ng * 4 + nt) * 8) * ROW_BYTES + off, bv[nt]);
#pragma unroll
                for (int s01 = 0; s01 < 2; s01++) {
#pragma unroll
                    for (int mt = 0; mt < 2; mt++)
#pragma unroll
                        for (int nt = 0; nt < 4; nt++)
                            mma_tf32(acc[mt][ng * 4 + nt],
                                     av0[mt][2 * s01], av1[mt][2 * s01],
                                     av0[mt][2 * s01 + 1], av1[mt][2 * s01 + 1],
                                     bv[nt][2 * s01], bv[nt][2 * s01 + 1]);
                }
            }
        }
        __syncthreads();
    }

    // ---------------- epilogue ----------------
    const int q = kq;

    if (EPI == 0) {
        // silu -> g_H, tf32-rounded, 32-block permuted (g_H is GEMM2's A).
        const int m0 = 2 * q, m1 = 2 * q + 1;
#pragma unroll
        for (int mt = 0; mt < 2; mt++) {
            int n = row0 + wm * 32 + mt * 16 + rq;
#pragma unroll
            for (int nt = 0; nt < 8; nt++) {
                const int s8 = nt & 3;
                const int p0 = (m0 & 3) * 8 + s8 * 2 + (m0 >> 2);
                const int p1 = (m1 & 3) * 8 + s8 * 2 + (m1 >> 2);
                const int gb32 = col0 + wn * 64 + (nt >> 2) * 32;
                float* d0 = g_H + (size_t)n * G_DIM + gb32;
                float* d1 = g_H + (size_t)(n + 8) * G_DIM + gb32;
                d0[p0] = rnd_tf32(silu_f(acc[mt][nt][0]));
                d0[p1] = rnd_tf32(silu_f(acc[mt][nt][1]));
                d1[p0] = rnd_tf32(silu_f(acc[mt][nt][2]));
                d1[p1] = rnd_tf32(silu_f(acc[mt][nt][3]));
            }
        }
    } else {
        // bias + causal depthwise conv + silu -> out
        const int halfd = q >> 1;
        const int wa = (q & 1) * 2;
#pragma unroll
        for (int nt = 0; nt < 8; nt++) {
            const int cb = col0 + wn * 64 + nt * 8;
            const int d  = (cb >> 2) + halfd;
            const float bias0 = b2[cb + 2 * q];
            const float bias1 = b2[cb + 2 * q + 1];
#pragma unroll
            for (int mt = 0; mt < 2; mt++) {
#pragma unroll
                for (int h = 0; h < 2; h++) {
                    const int n = row0 + wm * 32 + mt * 16 + rq + h * 8;
                    const int bb = n >> 12;
                    const int t  = n & (T_LEN - 1);
                    const float k0 = acc[mt][nt][2 * h + 0] + bias0;
                    const float k1 = acc[mt][nt][2 * h + 1] + bias1;
                    const float* xb = X + (size_t)bb * T_LEN * D_H + d;
                    float partial = 0.0f;
                    const int tt0 = t - (KW - 1) + wa;
                    if (tt0 >= 0)     partial = fmaf(xb[(size_t)tt0 * D_H], k0, partial);
                    if (tt0 + 1 >= 0) partial = fmaf(xb[(size_t)(tt0 + 1) * D_H], k1, partial);
                    const float tot = partial + __shfl_xor_sync(0xffffffffu, partial, 1);
                    if ((q & 1) == 0)
                        out[(size_t)n * D_H + d] = silu_f(tot);
                }
            }
        }
    }
}

// ---------------------------------------------------------------------------
extern "C" void kernel_launch(void* const* d_in, const int* in_sizes, int n_in,
                              void* d_out, int out_size) {
    const float* x  = (const float*)d_in[0];
    const float* w1 = (const float*)d_in[1];
    const float* w2 = (const float*)d_in[2];
    const float* b2 = (const float*)d_in[3];
    float* out = (float*)d_out;

    cudaFuncSetAttribute(gemm_mma<0>, cudaFuncAttributeMaxDynamicSharedMemorySize, SMEM_TOTAL);
    cudaFuncSetAttribute(gemm_mma<1>, cudaFuncAttributeMaxDynamicSharedMemorySize, SMEM_TOTAL);

    cvt_perm_kernel<0><<<(NROWS * D_H + 255) / 256, 256>>>(x,  NROWS * D_H);
    cvt_perm_kernel<1><<<(G_DIM * D_H + 255) / 256, 256>>>(w1, G_DIM * D_H);
    cvt_perm_kernel<2><<<(FLATC * G_DIM + 255) / 256, 256>>>(w2, FLATC * G_DIM);

    dim3 blk(256);
    dim3 g1(G_DIM / BN, NROWS / BM);    // (16, 64)
    gemm_mma<0><<<g1, blk, SMEM_TOTAL>>>(nullptr, nullptr, nullptr);

    dim3 g2(FLATC / BN, NROWS / BM);    // (64, 64)
    gemm_mma<1><<<g2, blk, SMEM_TOTAL>>>(x, b2, out);
}

// round 9
// speedup vs baseline: 2.1729x; 2.1729x over previous
#include <cuda_runtime.h>
#include <cuda_fp16.h>
#include <cstdint>

// ---------------- problem constants ----------------
#define D_H   2048
#define T_LEN 4096
#define NROWS 8192
#define G_DIM 2048
#define KW    4
#define FLATC 8192
#define KDIM  2048

// ---------------- tiling ----------------
#define BM 128
#define BN 128
#define BK 64                               // 64 fp16 = 128B per row
#define KCHUNKS (KDIM / BK)                 // 32
#define ROW_BYTES 160                       // 128B data + 32B pad (bank-verified)
#define SM_BOFF (BM * ROW_BYTES)            // 20480
#define STAGE_BYTES (2 * BM * ROW_BYTES)    // 40960
#define SMEM_TOTAL (2 * STAGE_BYTES)        // 81920

// ---------------- device scratch: fp16(rne), 16-block k-permuted ----------------
// perm within each 16-block: newpos(k) = (k&1) + ((k>>1)&3)*4 + ((k&8)>>2)
// inverse: k(p) = 2*(p>>2) + (p&1) + 8*((p>>1)&1)
__device__ __half g_H  [(size_t)NROWS * G_DIM];
__device__ __half g_xc [(size_t)NROWS * D_H];
__device__ __half g_w1c[(size_t)G_DIM * D_H];
__device__ __half g_w2c[(size_t)FLATC * G_DIM];

__device__ __forceinline__ float silu_f(float v) { return v / (1.0f + __expf(-v)); }

__device__ __forceinline__ void cp_async16(uint32_t dst, const void* src) {
    asm volatile("cp.async.cg.shared.global [%0], [%1], 16;" :: "r"(dst), "l"(src));
}
__device__ __forceinline__ uint32_t smem_u32(const void* p) {
    uint32_t a;
    asm("{ .reg .u64 t; cvta.to.shared.u64 t, %1; cvt.u32.u64 %0, t; }" : "=r"(a) : "l"(p));
    return a;
}
__device__ __forceinline__ void lds64(uint32_t addr, uint32_t& x, uint32_t& y) {
    asm volatile("ld.shared.v2.b32 {%0,%1}, [%2];" : "=r"(x), "=r"(y) : "r"(addr));
}
__device__ __forceinline__ void mma_f16(float c[4], uint32_t a0, uint32_t a1,
                                        uint32_t a2, uint32_t a3,
                                        uint32_t b0, uint32_t b1) {
    asm volatile(
        "mma.sync.aligned.m16n8k16.row.col.f32.f16.f16.f32 "
        "{%0,%1,%2,%3}, {%4,%5,%6,%7}, {%8,%9}, {%0,%1,%2,%3};"
        : "+f"(c[0]), "+f"(c[1]), "+f"(c[2]), "+f"(c[3])
        : "r"(a0), "r"(a1), "r"(a2), "r"(a3), "r"(b0), "r"(b1));
}

// ---------------- pre-convert: fp32 -> fp16(rne) + 16-block k-permute ----------
template <int WHICH>
__global__ __launch_bounds__(256)
void cvt_perm_kernel(const float* __restrict__ src, int nelem) {
    __half* dst = (WHICH == 0) ? g_xc : (WHICH == 1) ? g_w1c : g_w2c;
    int i = blockIdx.x * 256 + threadIdx.x;
    if (i < nelem) {
        int base = i & ~15;
        int p = i & 15;
        int k = 2 * (p >> 2) + (p & 1) + 8 * ((p >> 1) & 1);
        dst[base + p] = __float2half_rn(src[base + k]);
    }
}

// ---------------- tile loader: A 128xBK + B 128xBK (fp16) via cp.async --------
__device__ __forceinline__ void load_chunk(const __half* __restrict__ A,
                                           const __half* __restrict__ B,
                                           uint32_t stagebase, int k0,
                                           int row0, int col0, int tid) {
#pragma unroll
    for (int j = 0; j < 4; j++) {
        int idx = tid + 256 * j;
        int r = idx >> 3, c = idx & 7;
        cp_async16(stagebase + r * ROW_BYTES + c * 16,
                   A + (size_t)(row0 + r) * KDIM + k0 + c * 8);
    }
#pragma unroll
    for (int j = 0; j < 4; j++) {
        int idx = tid + 256 * j;
        int r = idx >> 3, c = idx & 7;
        cp_async16(stagebase + SM_BOFF + r * ROW_BYTES + c * 16,
                   B + (size_t)(col0 + r) * KDIM + k0 + c * 8);
    }
}

// ---------------- main GEMM: C[128x128] = A[128x2048] * B[128x2048]^T ----------
template <int EPI>
__global__ __launch_bounds__(256, 2)
void gemm_mma(const float* __restrict__ X,
              const float* __restrict__ b2,
              float* __restrict__ out) {
    const __half* A = (EPI == 0) ? (const __half*)g_xc : (const __half*)g_H;
    const __half* B = (EPI == 0) ? (const __half*)g_w1c : (const __half*)g_w2c;

    extern __shared__ char smem[];
    const uint32_t sb = smem_u32(smem);
    const int tid  = threadIdx.x;
    const int lane = tid & 31;
    const int warp = tid >> 5;
    const int wm = warp & 3;
    const int wn = warp >> 2;
    const int row0 = blockIdx.y * BM;
    const int col0 = blockIdx.x * BN;
    const int rq = lane >> 2;   // 0..7
    const int kq = lane & 3;    // 0..3

    float acc[2][8][4];
#pragma unroll
    for (int i = 0; i < 2; i++)
#pragma unroll
        for (int j = 0; j < 8; j++)
#pragma unroll
            for (int k = 0; k < 4; k++) acc[i][j][k] = 0.0f;

    load_chunk(A, B, sb, 0, row0, col0, tid);
    asm volatile("cp.async.commit_group;" ::: "memory");

    const uint32_t arow0 = wm * 32 + rq;
    const uint32_t brow0 = wn * 64 + rq;
    const uint32_t kqoff = kq * 8;           // 4 halves = 8B per thread span

    for (int i = 0; i < KCHUNKS; i++) {
        if (i + 1 < KCHUNKS) {
            load_chunk(A, B, sb + ((i + 1) & 1) * STAGE_BYTES, (i + 1) * BK, row0, col0, tid);
            asm volatile("cp.async.commit_group;" ::: "memory");
            asm volatile("cp.async.wait_group 1;" ::: "memory");
        } else {
            asm volatile("cp.async.wait_group 0;" ::: "memory");
        }
        __syncthreads();

        const uint32_t aB = sb + (i & 1) * STAGE_BYTES;
        const uint32_t bB = aB + SM_BOFF;

#pragma unroll
        for (int s = 0; s < 4; s++) {            // 4 k-steps of 16
            const uint32_t koff = s * 32 + kqoff;
            uint32_t af[2][4];
#pragma unroll
            for (int mt = 0; mt < 2; mt++) {
                uint32_t r = arow0 + mt * 16;
                lds64(aB + r * ROW_BYTES + koff, af[mt][0], af[mt][2]);
                lds64(aB + (r + 8) * ROW_BYTES + koff, af[mt][1], af[mt][3]);
            }
            uint32_t bf[8][2];
#pragma unroll
            for (int nt = 0; nt < 8; nt++)
                lds64(bB + (brow0 + nt * 8) * ROW_BYTES + koff, bf[nt][0], bf[nt][1]);
#pragma unroll
            for (int mt = 0; mt < 2; mt++)
#pragma unroll
                for (int nt = 0; nt < 8; nt++)
                    mma_f16(acc[mt][nt], af[mt][0], af[mt][1], af[mt][2], af[mt][3],
                            bf[nt][0], bf[nt][1]);
        }
        __syncthreads();
    }

    // ---------------- epilogue ----------------
    const int q = kq;

    if (EPI == 0) {
        // silu -> g_H (fp16, 16-block permuted). Thread's two columns within a
        // 16-block land at adjacent positions p0 = q*4 + (nt&1)*2, p0+1 -> half2.
        const int p0 = q * 4;
#pragma unroll
        for (int mt = 0; mt < 2; mt++) {
            int n = row0 + wm * 32 + mt * 16 + rq;
#pragma unroll
            for (int nt = 0; nt < 8; nt++) {
                const int base16 = col0 + wn * 64 + (nt >> 1) * 16;
                const int pp = p0 + (nt & 1) * 2;
                __half2 v0 = __floats2half2_rn(silu_f(acc[mt][nt][0]), silu_f(acc[mt][nt][1]));
                __half2 v1 = __floats2half2_rn(silu_f(acc[mt][nt][2]), silu_f(acc[mt][nt][3]));
                *(__half2*)(g_H + (size_t)n * G_DIM + base16 + pp) = v0;
                *(__half2*)(g_H + (size_t)(n + 8) * G_DIM + base16 + pp) = v1;
            }
        }
    } else {
        // bias + causal depthwise conv + silu -> out (round-3/5-verified logic)
        const int halfd = q >> 1;
        const int wa = (q & 1) * 2;
#pragma unroll
        for (int nt = 0; nt < 8; nt++) {
            const int cb = col0 + wn * 64 + nt * 8;
            const int d  = (cb >> 2) + halfd;
            const float bias0 = b2[cb + 2 * q];
            const float bias1 = b2[cb + 2 * q + 1];
#pragma unroll
            for (int mt = 0; mt < 2; mt++) {
#pragma unroll
                for (int h = 0; h < 2; h++) {
                    const int n = row0 + wm * 32 + mt * 16 + rq + h * 8;
                    const int bb = n >> 12;
                    const int t  = n & (T_LEN - 1);
                    const float k0 = acc[mt][nt][2 * h + 0] + bias0;
                    const float k1 = acc[mt][nt][2 * h + 1] + bias1;
                    const float* xb = X + (size_t)bb * T_LEN * D_H + d;
                    float partial = 0.0f;
                    const int tt0 = t - (KW - 1) + wa;
                    if (tt0 >= 0)     partial = fmaf(xb[(size_t)tt0 * D_H], k0, partial);
                    if (tt0 + 1 >= 0) partial = fmaf(xb[(size_t)(tt0 + 1) * D_H], k1, partial);
                    const float tot = partial + __shfl_xor_sync(0xffffffffu, partial, 1);
                    if ((q & 1) == 0)
                        out[(size_t)n * D_H + d] = silu_f(tot);
                }
            }
        }
    }
}

// ---------------------------------------------------------------------------
extern "C" void kernel_launch(void* const* d_in, const int* in_sizes, int n_in,
                              void* d_out, int out_size) {
    const float* x  = (const float*)d_in[0];
    const float* w1 = (const float*)d_in[1];
    const float* w2 = (const float*)d_in[2];
    const float* b2 = (const float*)d_in[3];
    float* out = (float*)d_out;

    cudaFuncSetAttribute(gemm_mma<0>, cudaFuncAttributeMaxDynamicSharedMemorySize, SMEM_TOTAL);
    cudaFuncSetAttribute(gemm_mma<1>, cudaFuncAttributeMaxDynamicSharedMemorySize, SMEM_TOTAL);

    cvt_perm_kernel<0><<<(NROWS * D_H + 255) / 256, 256>>>(x,  NROWS * D_H);
    cvt_perm_kernel<1><<<(G_DIM * D_H + 255) / 256, 256>>>(w1, G_DIM * D_H);
    cvt_perm_kernel<2><<<(FLATC * G_DIM + 255) / 256, 256>>>(w2, FLATC * G_DIM);

    dim3 blk(256);
    dim3 g1(G_DIM / BN, NROWS / BM);    // (16, 64)
    gemm_mma<0><<<g1, blk, SMEM_TOTAL>>>(nullptr, nullptr, nullptr);

    dim3 g2(FLATC / BN, NROWS / BM);    // (64, 64)
    gemm_mma<1><<<g2, blk, SMEM_TOTAL>>>(x, b2, out);
}

// round 12
// speedup vs baseline: 2.7544x; 1.2676x over previous
#include <cuda_runtime.h>
#include <cuda_fp16.h>
#include <cstdint>

// ---------------- problem constants ----------------
#define D_H   2048
#define T_LEN 4096
#define NROWS 8192
#define G_DIM 2048
#define KW    4
#define FLATC 8192
#define KDIM  2048

// ---------------- tiling ----------------
#define BM 128
#define BN 128
#define BK 64                               // 64 fp16 = 128B per row (SW128 native)
#define KCHUNKS (KDIM / BK)                 // 32
#define NSTAGE 3
#define TILE_BYTES (BM * 128)               // 16384
#define STAGE_BYTES (2 * TILE_BYTES)        // 32768 (A + B)
#define SMEM_TOTAL (NSTAGE * STAGE_BYTES)   // 98304

// ---------------- device scratch: fp16(rne), plain K-major ----------------
__device__ __half g_H  [(size_t)NROWS * G_DIM];
__device__ __half g_xc [(size_t)NROWS * D_H];
__device__ __half g_w1c[(size_t)G_DIM * D_H];
__device__ __half g_w2c[(size_t)FLATC * G_DIM];

__device__ __forceinline__ float silu_f(float v) { return v / (1.0f + __expf(-v)); }

__device__ __forceinline__ void cp_async16(uint32_t dst, const void* src) {
    asm volatile("cp.async.cg.shared.global [%0], [%1], 16;" :: "r"(dst), "l"(src));
}
__device__ __forceinline__ uint32_t smem_u32(const void* p) {
    uint32_t a;
    asm("{ .reg .u64 t; cvta.to.shared.u64 t, %1; cvt.u32.u64 %0, t; }" : "=r"(a) : "l"(p));
    return a;
}
__device__ __forceinline__ void ldmatrix_x4(uint32_t addr, uint32_t& r0, uint32_t& r1,
                                            uint32_t& r2, uint32_t& r3) {
    asm volatile("ldmatrix.sync.aligned.m8n8.x4.shared.b16 {%0,%1,%2,%3}, [%4];"
                 : "=r"(r0), "=r"(r1), "=r"(r2), "=r"(r3) : "r"(addr));
}
__device__ __forceinline__ void mma_f16(float c[4], uint32_t a0, uint32_t a1,
                                        uint32_t a2, uint32_t a3,
                                        uint32_t b0, uint32_t b1) {
    asm volatile(
        "mma.sync.aligned.m16n8k16.row.col.f32.f16.f16.f32 "
        "{%0,%1,%2,%3}, {%4,%5,%6,%7}, {%8,%9}, {%0,%1,%2,%3};"
        : "+f"(c[0]), "+f"(c[1]), "+f"(c[2]), "+f"(c[3])
        : "r"(a0), "r"(a1), "r"(a2), "r"(a3), "r"(b0), "r"(b1));
}

// ---------------- pre-convert: fp32 -> fp16(rne), plain layout ----------------
template <int WHICH>
__global__ __launch_bounds__(256)
void cvt_kernel(const float* __restrict__ src, int n8) {
    __half* dst = (WHICH == 0) ? g_xc : (WHICH == 1) ? g_w1c : g_w2c;
    int i = blockIdx.x * 256 + threadIdx.x;
    if (i < n8) {
        const float4* s = (const float4*)src + i * 2;
        float4 lo = s[0], hi = s[1];
        __half2 h[4];
        h[0] = __floats2half2_rn(lo.x, lo.y);
        h[1] = __floats2half2_rn(lo.z, lo.w);
        h[2] = __floats2half2_rn(hi.x, hi.y);
        h[3] = __floats2half2_rn(hi.z, hi.w);
        *(uint4*)(dst + (size_t)i * 8) = *(const uint4*)h;
    }
}

// ---------------- tile loader (SW128 swizzle: chunk c -> c ^ (r&7)) ----------
__device__ __forceinline__ void load_chunk(const __half* __restrict__ A,
                                           const __half* __restrict__ B,
                                           uint32_t stagebase, int k0,
                                           int row0, int col0, int tid) {
#pragma unroll
    for (int j = 0; j < 4; j++) {
        int idx = tid + 256 * j;
        int r = idx >> 3, c = idx & 7;
        cp_async16(stagebase + r * 128 + (c ^ (r & 7)) * 16,
                   A + (size_t)(row0 + r) * KDIM + k0 + c * 8);
    }
#pragma unroll
    for (int j = 0; j < 4; j++) {
        int idx = tid + 256 * j;
        int r = idx >> 3, c = idx & 7;
        cp_async16(stagebase + TILE_BYTES + r * 128 + (c ^ (r & 7)) * 16,
                   B + (size_t)(col0 + r) * KDIM + k0 + c * 8);
    }
}

// ---------------- main GEMM: C[128x128] = A[128x2048] * B[128x2048]^T ----------
template <int EPI>
__global__ __launch_bounds__(256, 2)
void gemm_mma(const float* __restrict__ X,
              const float* __restrict__ b2,
              float* __restrict__ out) {
    const __half* A = (EPI == 0) ? (const __half*)g_xc : (const __half*)g_H;
    const __half* B = (EPI == 0) ? (const __half*)g_w1c : (const __half*)g_w2c;

    extern __shared__ char smem[];
    const uint32_t sb = smem_u32(smem);
    const int tid  = threadIdx.x;
    const int lane = tid & 31;
    const int warp = tid >> 5;
    const int wm = warp & 3;
    const int wn = warp >> 2;
    const int row0 = blockIdx.y * BM;
    const int col0 = blockIdx.x * BN;
    const int rq = lane >> 2;
    const int kq = lane & 3;

    // ldmatrix per-lane address constants
    // A (.x4, 2 m-tiles): mat m: rowhalf=(m&1) -> (lane>>3)&1 ; chunkbit=(m>>1) -> lane>>4
    const int l7 = lane & 7;
    const uint32_t cbA = lane >> 4;
    uint32_t aRowOff[2], aSw[2];
#pragma unroll
    for (int mt = 0; mt < 2; mt++) {
        uint32_t r = wm * 32 + mt * 16 + l7 + ((lane >> 3) & 1) * 8;
        aRowOff[mt] = r * 128;
        aSw[mt] = r & 7;
    }
    // B (.x4, 2 n-tiles per load): mat m: ntile+=(m>>1) -> (lane>>4)&1 ; chunkbit=(m&1) -> (lane>>3)&1
    const uint32_t cbB = (lane >> 3) & 1;
    uint32_t bRowOff[4], bSw[4];
#pragma unroll
    for (int g = 0; g < 4; g++) {
        uint32_t r = wn * 64 + (2 * g + ((lane >> 4) & 1)) * 8 + l7;
        bRowOff[g] = r * 128;
        bSw[g] = r & 7;
    }

    float acc[2][8][4];
#pragma unroll
    for (int i = 0; i < 2; i++)
#pragma unroll
        for (int j = 0; j < 8; j++)
#pragma unroll
            for (int k = 0; k < 4; k++) acc[i][j][k] = 0.0f;

    // prologue: chunks 0,1 -> stages 0,1
    load_chunk(A, B, sb, 0, row0, col0, tid);
    asm volatile("cp.async.commit_group;" ::: "memory");
    load_chunk(A, B, sb + STAGE_BYTES, BK, row0, col0, tid);
    asm volatile("cp.async.commit_group;" ::: "memory");

    uint32_t stage = 0;
    for (int i = 0; i < KCHUNKS; i++) {
        if (i + 1 < KCHUNKS) asm volatile("cp.async.wait_group 1;" ::: "memory");
        else                 asm volatile("cp.async.wait_group 0;" ::: "memory");
        __syncthreads();

        if (i + 2 < KCHUNKS) {
            uint32_t ns = stage + 2; if (ns >= NSTAGE) ns -= NSTAGE;
            load_chunk(A, B, sb + ns * STAGE_BYTES, (i + 2) * BK, row0, col0, tid);
            asm volatile("cp.async.commit_group;" ::: "memory");
        }

        const uint32_t aBase = sb + stage * STAGE_BYTES;
        const uint32_t bBase = aBase + TILE_BYTES;

#pragma unroll
        for (int s = 0; s < 4; s++) {
            uint32_t a[2][4];
#pragma unroll
            for (int mt = 0; mt < 2; mt++)
                ldmatrix_x4(aBase + aRowOff[mt] + (((2 * s + cbA) ^ aSw[mt]) << 4),
                            a[mt][0], a[mt][1], a[mt][2], a[mt][3]);
#pragma unroll
            for (int g = 0; g < 4; g++) {
                uint32_t b0, b1, b2_, b3;
                ldmatrix_x4(bBase + bRowOff[g] + (((2 * s + cbB) ^ bSw[g]) << 4),
                            b0, b1, b2_, b3);
#pragma unroll
                for (int mt = 0; mt < 2; mt++) {
                    mma_f16(acc[mt][2 * g],     a[mt][0], a[mt][1], a[mt][2], a[mt][3], b0, b1);
                    mma_f16(acc[mt][2 * g + 1], a[mt][0], a[mt][1], a[mt][2], a[mt][3], b2_, b3);
                }
            }
        }
        stage = stage + 1; if (stage >= NSTAGE) stage -= NSTAGE;
    }

    // ---------------- epilogue ----------------
    const int q = kq;

    if (EPI == 0) {
        // silu -> g_H (fp16, plain K-major; no permutation needed with ldmatrix)
#pragma unroll
        for (int mt = 0; mt < 2; mt++) {
            int n = row0 + wm * 32 + mt * 16 + rq;
#pragma unroll
            for (int nt = 0; nt < 8; nt++) {
                int g = col0 + wn * 64 + nt * 8 + 2 * q;
                __half2 v0 = __floats2half2_rn(silu_f(acc[mt][nt][0]), silu_f(acc[mt][nt][1]));
                __half2 v1 = __floats2half2_rn(silu_f(acc[mt][nt][2]), silu_f(acc[mt][nt][3]));
                *(__half2*)(g_H + (size_t)n * G_DIM + g) = v0;
                *(__half2*)(g_H + (size_t)(n + 8) * G_DIM + g) = v1;
            }
        }
    } else {
        // bias + causal depthwise conv + silu -> out (verified since round 3)
        const int halfd = q >> 1;
        const int wa = (q & 1) * 2;
#pragma unroll
        for (int nt = 0; nt < 8; nt++) {
            const int cb = col0 + wn * 64 + nt * 8;
            const int d  = (cb >> 2) + halfd;
            const float bias0 = b2[cb + 2 * q];
            const float bias1 = b2[cb + 2 * q + 1];
#pragma unroll
            for (int mt = 0; mt < 2; mt++) {
#pragma unroll
                for (int h = 0; h < 2; h++) {
                    const int n = row0 + wm * 32 + mt * 16 + rq + h * 8;
                    const int bb = n >> 12;
                    const int t  = n & (T_LEN - 1);
                    const float k0 = acc[mt][nt][2 * h + 0] + bias0;
                    const float k1 = acc[mt][nt][2 * h + 1] + bias1;
                    const float* xb = X + (size_t)bb * T_LEN * D_H + d;
                    float partial = 0.0f;
                    const int tt0 = t - (KW - 1) + wa;
                    if (tt0 >= 0)     partial = fmaf(xb[(size_t)tt0 * D_H], k0, partial);
                    if (tt0 + 1 >= 0) partial = fmaf(xb[(size_t)(tt0 + 1) * D_H], k1, partial);
                    const float tot = partial + __shfl_xor_sync(0xffffffffu, partial, 1);
                    if ((q & 1) == 0)
                        out[(size_t)n * D_H + d] = silu_f(tot);
                }
            }
        }
    }
}

// ---------------------------------------------------------------------------
extern "C" void kernel_launch(void* const* d_in, const int* in_sizes, int n_in,
                              void* d_out, int out_size) {
    const float* x  = (const float*)d_in[0];
    const float* w1 = (const float*)d_in[1];
    const float* w2 = (const float*)d_in[2];
    const float* b2 = (const float*)d_in[3];
    float* out = (float*)d_out;

    cudaFuncSetAttribute(gemm_mma<0>, cudaFuncAttributeMaxDynamicSharedMemorySize, SMEM_TOTAL);
    cudaFuncSetAttribute(gemm_mma<1>, cudaFuncAttributeMaxDynamicSharedMemorySize, SMEM_TOTAL);

    cvt_kernel<0><<<(NROWS * D_H / 8 + 255) / 256, 256>>>(x,  NROWS * D_H / 8);
    cvt_kernel<1><<<(G_DIM * D_H / 8 + 255) / 256, 256>>>(w1, G_DIM * D_H / 8);
    cvt_kernel<2><<<(FLATC * G_DIM / 8 + 255) / 256, 256>>>(w2, FLATC * G_DIM / 8);

    dim3 blk(256);
    dim3 g1(G_DIM / BN, NROWS / BM);    // (16, 64)
    gemm_mma<0><<<g1, blk, SMEM_TOTAL>>>(nullptr, nullptr, nullptr);

    dim3 g2(FLATC / BN, NROWS / BM);    // (64, 64)
    gemm_mma<1><<<g2, blk, SMEM_TOTAL>>>(x, b2, out);
}